// round 16
// baseline (speedup 1.0000x reference)
#include <cuda_runtime.h>
#include <cuda_bf16.h>
#include <cuda_fp16.h>
#include <math.h>
#include <stdint.h>

#define SEQ 2048
#define DM 2048
#define NH 16
#define HD 128
#define QKVN (3*DM)

// Scratch (allocation-free rule: __device__ globals)
__device__ float g_qkv[SEQ * QKVN];     // [S, 3D]
// bf16 hi/lo split copies for tensor-core attention, [H][S][HD]
__device__ __nv_bfloat16 g_qh[NH*SEQ*HD], g_ql[NH*SEQ*HD];
__device__ __nv_bfloat16 g_kh[NH*SEQ*HD], g_kl[NH*SEQ*HD];
__device__ __nv_bfloat16 g_vh[NH*SEQ*HD], g_vl[NH*SEQ*HD];
// fp16 operands for projection GEMMs (A hi/lo 2-term, B single)
__device__ __half g_xh[SEQ*DM],   g_xl[SEQ*DM];     // A of QKV (hi/lo)
__device__ __half g_wqh[DM*QKVN];                   // B of QKV (single)
__device__ __half g_wdh[DM*DM];                     // B of dense (single)
__device__ __half g_ch[SEQ*DM],   g_cl[SEQ*DM];     // A of dense (ctx hi/lo)

// ---------------------------------------------------------------------------
// helpers
// ---------------------------------------------------------------------------
__device__ __forceinline__ void bsplit(float x, __nv_bfloat16& h, __nv_bfloat16& l)
{
    h = __float2bfloat16_rn(x);
    l = __float2bfloat16_rn(x - __bfloat162float(h));
}
__device__ __forceinline__ void ldsm4(uint32_t& r0, uint32_t& r1, uint32_t& r2,
                                      uint32_t& r3, uint32_t addr)
{
    asm volatile("ldmatrix.sync.aligned.m8n8.x4.shared.b16 {%0,%1,%2,%3}, [%4];"
                 : "=r"(r0), "=r"(r1), "=r"(r2), "=r"(r3) : "r"(addr));
}
__device__ __forceinline__ void ldsm4t(uint32_t& r0, uint32_t& r1, uint32_t& r2,
                                       uint32_t& r3, uint32_t addr)
{
    asm volatile("ldmatrix.sync.aligned.m8n8.x4.trans.shared.b16 {%0,%1,%2,%3}, [%4];"
                 : "=r"(r0), "=r"(r1), "=r"(r2), "=r"(r3) : "r"(addr));
}
// bf16 mma (flash)
__device__ __forceinline__ void mma16816(float* c, uint32_t a0, uint32_t a1,
                                         uint32_t a2, uint32_t a3,
                                         uint32_t b0, uint32_t b1)
{
    asm volatile(
        "mma.sync.aligned.m16n8k16.row.col.f32.bf16.bf16.f32 "
        "{%0,%1,%2,%3}, {%4,%5,%6,%7}, {%8,%9}, {%0,%1,%2,%3};"
        : "+f"(c[0]), "+f"(c[1]), "+f"(c[2]), "+f"(c[3])
        : "r"(a0), "r"(a1), "r"(a2), "r"(a3), "r"(b0), "r"(b1));
}
// fp16 mma (projection GEMMs)
__device__ __forceinline__ void mma16816h(float* c, uint32_t a0, uint32_t a1,
                                          uint32_t a2, uint32_t a3,
                                          uint32_t b0, uint32_t b1)
{
    asm volatile(
        "mma.sync.aligned.m16n8k16.row.col.f32.f16.f16.f32 "
        "{%0,%1,%2,%3}, {%4,%5,%6,%7}, {%8,%9}, {%0,%1,%2,%3};"
        : "+f"(c[0]), "+f"(c[1]), "+f"(c[2]), "+f"(c[3])
        : "r"(a0), "r"(a1), "r"(a2), "r"(a3), "r"(b0), "r"(b1));
}
__device__ __forceinline__ uint32_t packbf(float x, float y)
{
    __nv_bfloat162 t = __floats2bfloat162_rn(x, y);
    return *reinterpret_cast<uint32_t*>(&t);
}
__device__ __forceinline__ void split2(float x0, float x1, uint32_t& h, uint32_t& l)
{
    float h0 = __bfloat162float(__float2bfloat16_rn(x0));
    float h1 = __bfloat162float(__float2bfloat16_rn(x1));
    h = packbf(h0, h1);
    l = packbf(x0 - h0, x1 - h1);
}
// fp16 hi/lo split of a pair
__device__ __forceinline__ void split2h(float x0, float x1, uint32_t& h, uint32_t& l)
{
    __half2 hh = __floats2half2_rn(x0, x1);
    float h0 = __low2float(hh), h1 = __high2float(hh);
    __half2 ll = __floats2half2_rn(x0 - h0, x1 - h1);
    h = *reinterpret_cast<uint32_t*>(&hh);
    l = *reinterpret_cast<uint32_t*>(&ll);
}
__device__ __forceinline__ void cpa16(uint32_t saddr, const void* gaddr)
{
    asm volatile("cp.async.cg.shared.global [%0], [%1], 16;"
                 :: "r"(saddr), "l"(gaddr));
}
__device__ __forceinline__ void cpa_commit()
{
    asm volatile("cp.async.commit_group;" ::: "memory");
}
template <int N>
__device__ __forceinline__ void cpa_wait()
{
    asm volatile("cp.async.wait_group %0;" :: "n"(N) : "memory");
}

// ---------------------------------------------------------------------------
// presplits
// ---------------------------------------------------------------------------
__global__ void presplit2h_kernel(const float* __restrict__ src,
                                  __half* __restrict__ dh,
                                  __half* __restrict__ dl, int n2)
{
    int i = blockIdx.x * blockDim.x + threadIdx.x;
    if (i >= n2) return;
    float2 v = ((const float2*)src)[i];
    uint32_t h, l;
    split2h(v.x, v.y, h, l);
    ((uint32_t*)dh)[i] = h;
    ((uint32_t*)dl)[i] = l;
}
__global__ void presplit1h_kernel(const float* __restrict__ src,
                                  __half* __restrict__ dh, int n2)
{
    int i = blockIdx.x * blockDim.x + threadIdx.x;
    if (i >= n2) return;
    float2 v = ((const float2*)src)[i];
    __half2 hh = __floats2half2_rn(v.x, v.y);
    ((__half2*)dh)[i] = hh;
}

// ---------------------------------------------------------------------------
// fp16 2-term GEMM: C[M,N] = (Ah+Al)[M,K]*Bh[K,N] + bias[N]
// CTA tile 128x256, K-step 32, 8 warps as 2(m) x 4(n), warp tile 64x64.
// cp.async double-buffered staging.
// A smem [m][k] stride 40 (ldsm); B smem [k][n] stride 264 (ldsm.trans).
// ---------------------------------------------------------------------------
#define GA_STRIDE 40
#define GB_STRIDE 264
#define GA_BYTES  (128*GA_STRIDE*2)             // 10240
#define GB_BYTES  (32*GB_STRIDE*2)              // 16896
#define GBUF      (2*GA_BYTES + GB_BYTES)       // 37376
#define GEMM_SMEM (2*GBUF)                      // 74752

__global__ __launch_bounds__(256, 1)
void gemm_mma_kernel(const __half* __restrict__ Ah,
                     const __half* __restrict__ Al,
                     const __half* __restrict__ Bh,
                     const float* __restrict__ bias,
                     float* __restrict__ C, int N, int K)
{
    extern __shared__ char gsm[];
    const int tid = threadIdx.x;
    const int warp = tid >> 5, lane = tid & 31;
    const int g = lane >> 3, ri = lane & 7;
    const int wm = warp & 1, wn = warp >> 1;          // 2 x 4 warp grid
    const int m0 = blockIdx.y * 128, n0 = blockIdx.x * 256;

    // staging coords: A: 2 chunks/term, B: 4 chunks
    const int a_r = tid >> 2, a_c = (tid & 3) << 3;   // A rows +i*64, 32-k cols
    const int b_r = tid >> 5, b_c = (tid & 31) << 3;  // B rows +i*8, 256-n cols

    const uint32_t sbase = (uint32_t)__cvta_generic_to_shared(gsm);
    const int nk = K >> 5;

    auto load_tile = [&](int kt, int buf) {
        const uint32_t bb = sbase + buf * GBUF;
#pragma unroll
        for (int i = 0; i < 2; ++i) {
            size_t ga = (size_t)(m0 + a_r + i * 64) * K + kt * 32 + a_c;
            uint32_t sa = bb + (uint32_t)(((a_r + i*64) * GA_STRIDE + a_c) * 2);
            cpa16(sa,            Ah + ga);
            cpa16(sa + GA_BYTES, Al + ga);
        }
#pragma unroll
        for (int i = 0; i < 4; ++i) {
            size_t gb = (size_t)(kt * 32 + b_r + i * 8) * N + n0 + b_c;
            uint32_t sb = bb + 2*GA_BYTES + (uint32_t)(((b_r + i*8) * GB_STRIDE + b_c) * 2);
            cpa16(sb, Bh + gb);
        }
        cpa_commit();
    };

    float acc[4][8][4];
#pragma unroll
    for (int mf = 0; mf < 4; ++mf)
#pragma unroll
        for (int nf = 0; nf < 8; ++nf)
#pragma unroll
            for (int c = 0; c < 4; ++c) acc[mf][nf][c] = 0.f;

    // ldmatrix offsets: A rows wm*64 + mf*16, B cols wn*64 + nfp*16
    const uint32_t aoff = (uint32_t)(((wm*64 + ri + (g&1)*8) * GA_STRIDE + (g>>1)*8) * 2);
    const uint32_t boff = (uint32_t)(((ri + (g&1)*8) * GB_STRIDE + wn*64 + (g>>1)*8) * 2);

    load_tile(0, 0);
    load_tile(1, 1);
    cpa_wait<1>();
    __syncthreads();

    for (int kt = 0; kt < nk; ++kt) {
        const int buf = kt & 1;
        const uint32_t sAh = sbase + buf * GBUF;
        const uint32_t sAl = sAh + GA_BYTES;
        const uint32_t sBh = sAh + 2*GA_BYTES;

#pragma unroll
        for (int k16 = 0; k16 < 2; ++k16) {
            uint32_t ah[4][4], al[4][4], bh[4][4];
#pragma unroll
            for (int mf = 0; mf < 4; ++mf) {
                uint32_t o = aoff + (uint32_t)(mf * 16 * GA_STRIDE * 2) + k16 * 32;
                ldsm4(ah[mf][0], ah[mf][1], ah[mf][2], ah[mf][3], sAh + o);
                ldsm4(al[mf][0], al[mf][1], al[mf][2], al[mf][3], sAl + o);
            }
#pragma unroll
            for (int nfp = 0; nfp < 4; ++nfp) {
                uint32_t o = boff + (uint32_t)(k16 * 16 * GB_STRIDE * 2) + nfp * 32;
                ldsm4t(bh[nfp][0], bh[nfp][1], bh[nfp][2], bh[nfp][3], sBh + o);
            }
            // hi-term burst: 32 independent MMAs
#pragma unroll
            for (int mf = 0; mf < 4; ++mf)
#pragma unroll
                for (int nfp = 0; nfp < 4; ++nfp) {
                    mma16816h(acc[mf][2*nfp],   ah[mf][0],ah[mf][1],ah[mf][2],ah[mf][3], bh[nfp][0],bh[nfp][1]);
                    mma16816h(acc[mf][2*nfp+1], ah[mf][0],ah[mf][1],ah[mf][2],ah[mf][3], bh[nfp][2],bh[nfp][3]);
                }
            // lo-term burst
#pragma unroll
            for (int mf = 0; mf < 4; ++mf)
#pragma unroll
                for (int nfp = 0; nfp < 4; ++nfp) {
                    mma16816h(acc[mf][2*nfp],   al[mf][0],al[mf][1],al[mf][2],al[mf][3], bh[nfp][0],bh[nfp][1]);
                    mma16816h(acc[mf][2*nfp+1], al[mf][0],al[mf][1],al[mf][2],al[mf][3], bh[nfp][2],bh[nfp][3]);
                }
        }

        __syncthreads();
        if (kt + 2 < nk) load_tile(kt + 2, buf);
        if (kt + 1 < nk) {
            cpa_wait<1>();
            __syncthreads();
        }
    }

    // epilogue: add bias, store fp32
#pragma unroll
    for (int mf = 0; mf < 4; ++mf) {
        int row = m0 + wm * 64 + mf * 16 + (lane >> 2);
#pragma unroll
        for (int nf = 0; nf < 8; ++nf) {
            int col = n0 + wn * 64 + nf * 8 + 2 * (lane & 3);
            float b0 = bias[col], b1 = bias[col + 1];
            *(float2*)(C + (size_t)row * N + col) =
                make_float2(acc[mf][nf][0] + b0, acc[mf][nf][1] + b1);
            *(float2*)(C + (size_t)(row + 8) * N + col) =
                make_float2(acc[mf][nf][2] + b0, acc[mf][nf][3] + b1);
        }
    }
}

// ---------------------------------------------------------------------------
// RoPE + split qkv -> bf16 hi/lo Q,K,V in [H,S,HD]. Q pre-scaled by HD^-0.5.
// ---------------------------------------------------------------------------
__global__ void rope_split_kernel(const float* __restrict__ fc)
{
    int idx = blockIdx.x * blockDim.x + threadIdx.x;
    const int total = SEQ * NH * (HD / 2);
    if (idx >= total) return;
    int i = idx & 63;
    int h = (idx >> 6) & 15;
    int s = idx >> 10;
    float c  = fc[(s * 64 + i) * 2 + 0];
    float sn = fc[(s * 64 + i) * 2 + 1];
    const float* row = g_qkv + (size_t)s * QKVN;
    int d = h * HD + 2 * i;
    float q0 = row[d],           q1 = row[d + 1];
    float k0 = row[DM + d],      k1 = row[DM + d + 1];
    float v0 = row[2 * DM + d],  v1 = row[2 * DM + d + 1];
    const float qs = 0.08838834764831845f;   // 128^-0.5
    float qr0 = (q0 * c - q1 * sn) * qs;
    float qr1 = (q1 * c + q0 * sn) * qs;
    float kr0 = k0 * c - k1 * sn;
    float kr1 = k1 * c + k0 * sn;

    size_t o = ((size_t)h * SEQ + s) * HD + 2 * i;
    __nv_bfloat16 h0, l0, h1, l1;

    bsplit(qr0, h0, l0); bsplit(qr1, h1, l1);
    *(__nv_bfloat162*)&g_qh[o] = __nv_bfloat162(h0, h1);
    *(__nv_bfloat162*)&g_ql[o] = __nv_bfloat162(l0, l1);

    bsplit(kr0, h0, l0); bsplit(kr1, h1, l1);
    *(__nv_bfloat162*)&g_kh[o] = __nv_bfloat162(h0, h1);
    *(__nv_bfloat162*)&g_kl[o] = __nv_bfloat162(l0, l1);

    bsplit(v0, h0, l0); bsplit(v1, h1, l1);
    *(__nv_bfloat162*)&g_vh[o] = __nv_bfloat162(h0, h1);
    *(__nv_bfloat162*)&g_vl[o] = __nv_bfloat162(l0, l1);
}

// ---------------------------------------------------------------------------
// Tensor-core flash attention (bf16 hi/lo split, fp32 softmax/accum).
// Epilogue writes ctx as fp16 hi/lo (A of the dense GEMM).
// ---------------------------------------------------------------------------
#define FL_STRIDE 136
#define FL_Q_ELE  (128*FL_STRIDE)
#define FL_K_ELE  (64*FL_STRIDE)
#define FLASH_SMEM ((2*FL_Q_ELE + 4*FL_K_ELE) * 2)

__global__ __launch_bounds__(256, 1)
void flash_attn_mma_kernel()
{
    extern __shared__ __nv_bfloat16 sm[];
    __nv_bfloat16* Qh = sm;
    __nv_bfloat16* Ql = Qh + FL_Q_ELE;
    __nv_bfloat16* Kh = Ql + FL_Q_ELE;
    __nv_bfloat16* Kl = Kh + FL_K_ELE;
    __nv_bfloat16* Vh = Kl + FL_K_ELE;
    __nv_bfloat16* Vl = Vh + FL_K_ELE;

    const int h    = blockIdx.y;
    const int tid  = threadIdx.x;
    const int warp = tid >> 5, lane = tid & 31;
    const int g = lane >> 3, ri = lane & 7;

    const __nv_bfloat16* gQh = g_qh + (size_t)h * SEQ * HD;
    const __nv_bfloat16* gQl = g_ql + (size_t)h * SEQ * HD;
    const __nv_bfloat16* gKh = g_kh + (size_t)h * SEQ * HD;
    const __nv_bfloat16* gKl = g_kl + (size_t)h * SEQ * HD;
    const __nv_bfloat16* gVh = g_vh + (size_t)h * SEQ * HD;
    const __nv_bfloat16* gVl = g_vl + (size_t)h * SEQ * HD;

    const uint32_t sQh = (uint32_t)__cvta_generic_to_shared(Qh);
    const uint32_t sQl = (uint32_t)__cvta_generic_to_shared(Ql);
    const uint32_t sKh = (uint32_t)__cvta_generic_to_shared(Kh);
    const uint32_t sKl = (uint32_t)__cvta_generic_to_shared(Kl);
    const uint32_t sVh = (uint32_t)__cvta_generic_to_shared(Vh);
    const uint32_t sVl = (uint32_t)__cvta_generic_to_shared(Vl);

    const uint32_t aQoff = (uint32_t)(((warp*16 + ri + (g&1)*8) * FL_STRIDE + (g>>1)*8) * 2);
    const uint32_t bKoff = (uint32_t)(((ri + (g>>1)*8) * FL_STRIDE + (g&1)*8) * 2);
    const uint32_t bVoff = (uint32_t)(((ri + (g&1)*8) * FL_STRIDE + (g>>1)*8) * 2);

    const int bx = blockIdx.x;

    for (int pass = 0; pass < 2; ++pass) {
        const int qt = pass ? bx : (15 - bx);

        __syncthreads();
#pragma unroll
        for (int t = 0; t < 8; ++t) {
            int idx = tid + t * 256;
            int r = idx >> 4, c8 = (idx & 15) << 3;
            size_t gsrc = (size_t)(qt * 128 + r) * HD + c8;
            *(uint4*)&Qh[r * FL_STRIDE + c8] = *(const uint4*)&gQh[gsrc];
            *(uint4*)&Ql[r * FL_STRIDE + c8] = *(const uint4*)&gQl[gsrc];
        }

        float O[16][4];
        float m0 = -1e30f, m1 = -1e30f, l0 = 0.f, l1 = 0.f;
#pragma unroll
        for (int t = 0; t < 16; ++t)
#pragma unroll
            for (int c = 0; c < 4; ++c) O[t][c] = 0.f;

        const int jmax = 2 * qt + 1;
        for (int j = 0; j <= jmax; ++j) {
            __syncthreads();
#pragma unroll
            for (int t = 0; t < 4; ++t) {
                int idx = tid + t * 256;
                int r = idx >> 4, c8 = (idx & 15) << 3;
                size_t gsrc = (size_t)(j * 64 + r) * HD + c8;
                *(uint4*)&Kh[r * FL_STRIDE + c8] = *(const uint4*)&gKh[gsrc];
                *(uint4*)&Kl[r * FL_STRIDE + c8] = *(const uint4*)&gKl[gsrc];
                *(uint4*)&Vh[r * FL_STRIDE + c8] = *(const uint4*)&gVh[gsrc];
                *(uint4*)&Vl[r * FL_STRIDE + c8] = *(const uint4*)&gVl[gsrc];
            }
            __syncthreads();

            float S[8][4];
#pragma unroll
            for (int t = 0; t < 8; ++t)
#pragma unroll
                for (int c = 0; c < 4; ++c) S[t][c] = 0.f;

#pragma unroll
            for (int kc = 0; kc < 8; ++kc) {
                uint32_t qh0,qh1,qh2,qh3, ql0,ql1,ql2,ql3;
                ldsm4(qh0,qh1,qh2,qh3, sQh + aQoff + kc*32);
                ldsm4(ql0,ql1,ql2,ql3, sQl + aQoff + kc*32);
#pragma unroll
                for (int np = 0; np < 4; ++np) {
                    uint32_t kh0,kh1,kh2,kh3, kl0,kl1,kl2,kl3;
                    uint32_t o = bKoff + (uint32_t)(np*16*FL_STRIDE*2) + kc*32;
                    ldsm4(kh0,kh1,kh2,kh3, sKh + o);
                    ldsm4(kl0,kl1,kl2,kl3, sKl + o);
                    mma16816(S[2*np],   qh0,qh1,qh2,qh3, kh0,kh1);
                    mma16816(S[2*np],   ql0,ql1,ql2,ql3, kh0,kh1);
                    mma16816(S[2*np],   qh0,qh1,qh2,qh3, kl0,kl1);
                    mma16816(S[2*np+1], qh0,qh1,qh2,qh3, kh2,kh3);
                    mma16816(S[2*np+1], ql0,ql1,ql2,ql3, kh2,kh3);
                    mma16816(S[2*np+1], qh0,qh1,qh2,qh3, kl2,kl3);
                }
            }

            const int row0 = qt * 128 + warp * 16 + (lane >> 2);
            if (j >= 2 * qt) {
#pragma unroll
                for (int t = 0; t < 8; ++t) {
                    int col = j * 64 + t * 8 + 2 * (lane & 3);
#pragma unroll
                    for (int c = 0; c < 4; ++c) {
                        int cc = col + (c & 1);
                        int rr = row0 + ((c >= 2) ? 8 : 0);
                        if (cc > rr) S[t][c] = -1e30f;
                    }
                }
            }

            float mx0 = -1e30f, mx1 = -1e30f;
#pragma unroll
            for (int t = 0; t < 8; ++t) {
                mx0 = fmaxf(mx0, fmaxf(S[t][0], S[t][1]));
                mx1 = fmaxf(mx1, fmaxf(S[t][2], S[t][3]));
            }
            mx0 = fmaxf(mx0, __shfl_xor_sync(0xffffffffu, mx0, 1));
            mx0 = fmaxf(mx0, __shfl_xor_sync(0xffffffffu, mx0, 2));
            mx1 = fmaxf(mx1, __shfl_xor_sync(0xffffffffu, mx1, 1));
            mx1 = fmaxf(mx1, __shfl_xor_sync(0xffffffffu, mx1, 2));
            float mn0 = fmaxf(m0, mx0), mn1 = fmaxf(m1, mx1);
            float al0 = __expf(m0 - mn0), al1 = __expf(m1 - mn1);
            float rs0 = 0.f, rs1 = 0.f;
#pragma unroll
            for (int t = 0; t < 8; ++t) {
                S[t][0] = __expf(S[t][0] - mn0);
                S[t][1] = __expf(S[t][1] - mn0);
                S[t][2] = __expf(S[t][2] - mn1);
                S[t][3] = __expf(S[t][3] - mn1);
                rs0 += S[t][0] + S[t][1];
                rs1 += S[t][2] + S[t][3];
            }
            rs0 += __shfl_xor_sync(0xffffffffu, rs0, 1);
            rs0 += __shfl_xor_sync(0xffffffffu, rs0, 2);
            rs1 += __shfl_xor_sync(0xffffffffu, rs1, 1);
            rs1 += __shfl_xor_sync(0xffffffffu, rs1, 2);
            l0 = l0 * al0 + rs0;  m0 = mn0;
            l1 = l1 * al1 + rs1;  m1 = mn1;
#pragma unroll
            for (int t = 0; t < 16; ++t) {
                O[t][0] *= al0; O[t][1] *= al0;
                O[t][2] *= al1; O[t][3] *= al1;
            }

#pragma unroll
            for (int kc2 = 0; kc2 < 4; ++kc2) {
                uint32_t ph0,ph1,ph2,ph3, pl0,pl1,pl2,pl3;
                split2(S[2*kc2][0],   S[2*kc2][1],   ph0, pl0);
                split2(S[2*kc2][2],   S[2*kc2][3],   ph1, pl1);
                split2(S[2*kc2+1][0], S[2*kc2+1][1], ph2, pl2);
                split2(S[2*kc2+1][2], S[2*kc2+1][3], ph3, pl3);
#pragma unroll
                for (int np = 0; np < 8; ++np) {
                    uint32_t vh0,vh1,vh2,vh3, vl0,vl1,vl2,vl3;
                    uint32_t o = bVoff + (uint32_t)(kc2*16*FL_STRIDE*2) + np*32;
                    ldsm4t(vh0,vh1,vh2,vh3, sVh + o);
                    ldsm4t(vl0,vl1,vl2,vl3, sVl + o);
                    mma16816(O[2*np],   ph0,ph1,ph2,ph3, vh0,vh1);
                    mma16816(O[2*np],   pl0,pl1,pl2,pl3, vh0,vh1);
                    mma16816(O[2*np],   ph0,ph1,ph2,ph3, vl0,vl1);
                    mma16816(O[2*np+1], ph0,ph1,ph2,ph3, vh2,vh3);
                    mma16816(O[2*np+1], pl0,pl1,pl2,pl3, vh2,vh3);
                    mma16816(O[2*np+1], ph0,ph1,ph2,ph3, vl2,vl3);
                }
            }
        }

        // normalize + store ctx as fp16 hi/lo, [S, D] layout (head h cols)
        float inv0 = 1.f / l0, inv1 = 1.f / l1;
        int grow = qt * 128 + warp * 16 + (lane >> 2);
        size_t off0 = (size_t)grow * DM + h * HD;
        size_t off1 = off0 + (size_t)8 * DM;
#pragma unroll
        for (int t = 0; t < 16; ++t) {
            int c = t * 8 + 2 * (lane & 3);
            uint32_t hh, ll;
            split2h(O[t][0] * inv0, O[t][1] * inv0, hh, ll);
            *(uint32_t*)&g_ch[off0 + c] = hh;
            *(uint32_t*)&g_cl[off0 + c] = ll;
            split2h(O[t][2] * inv1, O[t][3] * inv1, hh, ll);
            *(uint32_t*)&g_ch[off1 + c] = hh;
            *(uint32_t*)&g_cl[off1 + c] = ll;
        }
    }
}

// ---------------------------------------------------------------------------
extern "C" void kernel_launch(void* const* d_in, const int* in_sizes, int n_in,
                              void* d_out, int out_size)
{
    const float* x    = (const float*)d_in[0];
    const float* fc   = (const float*)d_in[1];
    // d_in[2] = input_pos (arange -> identity scatter, unused)
    const float* Wqkv = (const float*)d_in[3];
    const float* bqkv = (const float*)d_in[4];
    const float* Wd   = (const float*)d_in[5];
    const float* bd   = (const float*)d_in[6];
    float* out = (float*)d_out;

    float* qkv_p;
    cudaGetSymbolAddress((void**)&qkv_p, g_qkv);
    __half *xh, *xl, *wqh, *wdh, *ch, *cl;
    cudaGetSymbolAddress((void**)&xh,  g_xh);  cudaGetSymbolAddress((void**)&xl,  g_xl);
    cudaGetSymbolAddress((void**)&wqh, g_wqh);
    cudaGetSymbolAddress((void**)&wdh, g_wdh);
    cudaGetSymbolAddress((void**)&ch,  g_ch);  cudaGetSymbolAddress((void**)&cl,  g_cl);

    cudaFuncSetAttribute(gemm_mma_kernel,
                         cudaFuncAttributeMaxDynamicSharedMemorySize, GEMM_SMEM);
    cudaFuncSetAttribute(flash_attn_mma_kernel,
                         cudaFuncAttributeMaxDynamicSharedMemorySize, FLASH_SMEM);

    // 0) presplit inputs: x -> fp16 hi/lo, weights -> fp16 single
    presplit2h_kernel<<<(SEQ*DM/2 + 255)/256, 256>>>(x, xh, xl, SEQ*DM/2);
    presplit1h_kernel<<<(DM*QKVN/2 + 255)/256, 256>>>(Wqkv, wqh, DM*QKVN/2);
    presplit1h_kernel<<<(DM*DM/2 + 255)/256, 256>>>(Wd, wdh, DM*DM/2);

    // 1) QKV projection (fp16 2-term mma): [S,D] @ [D,3D] + bias
    gemm_mma_kernel<<<dim3(QKVN/256, SEQ/128), 256, GEMM_SMEM>>>(
        xh, xl, wqh, bqkv, qkv_p, QKVN, DM);

    // 2) RoPE + bf16 hi/lo split into [H,S,HD] Q/K/V (Q pre-scaled)
    rope_split_kernel<<<(SEQ * NH * (HD / 2) + 255) / 256, 256>>>(fc);

    // 3) causal flash attention (paired q-tiles: 8 x 16 CTAs); writes ctx fp16 hi/lo
    flash_attn_mma_kernel<<<dim3(8, NH), 256, FLASH_SMEM>>>();

    // 4) output projection (fp16 2-term mma): ctx @ Wdense + bias
    gemm_mma_kernel<<<dim3(DM/256, SEQ/128), 256, GEMM_SMEM>>>(
        ch, cl, wdh, bd, out, DM, DM);
}

// round 17
// speedup vs baseline: 1.0362x; 1.0362x over previous
#include <cuda_runtime.h>
#include <cuda_bf16.h>
#include <cuda_fp16.h>
#include <math.h>
#include <stdint.h>

#define SEQ 2048
#define DM 2048
#define NH 16
#define HD 128
#define QKVN (3*DM)

// Scratch (allocation-free rule: __device__ globals)
// bf16 hi/lo split copies for tensor-core attention, [H][S][HD]
__device__ __nv_bfloat16 g_qh[NH*SEQ*HD], g_ql[NH*SEQ*HD];
__device__ __nv_bfloat16 g_kh[NH*SEQ*HD], g_kl[NH*SEQ*HD];
__device__ __nv_bfloat16 g_vh[NH*SEQ*HD], g_vl[NH*SEQ*HD];
// fp16 operands for projection GEMMs (A hi/lo 2-term, B single)
__device__ __half g_xh[SEQ*DM],   g_xl[SEQ*DM];     // A of QKV (hi/lo)
__device__ __half g_wqh[DM*QKVN];                   // B of QKV (single)
__device__ __half g_wdh[DM*DM];                     // B of dense (single)
__device__ __half g_ch[SEQ*DM],   g_cl[SEQ*DM];     // A of dense (ctx hi/lo)

// ---------------------------------------------------------------------------
// helpers
// ---------------------------------------------------------------------------
__device__ __forceinline__ void ldsm4(uint32_t& r0, uint32_t& r1, uint32_t& r2,
                                      uint32_t& r3, uint32_t addr)
{
    asm volatile("ldmatrix.sync.aligned.m8n8.x4.shared.b16 {%0,%1,%2,%3}, [%4];"
                 : "=r"(r0), "=r"(r1), "=r"(r2), "=r"(r3) : "r"(addr));
}
__device__ __forceinline__ void ldsm4t(uint32_t& r0, uint32_t& r1, uint32_t& r2,
                                       uint32_t& r3, uint32_t addr)
{
    asm volatile("ldmatrix.sync.aligned.m8n8.x4.trans.shared.b16 {%0,%1,%2,%3}, [%4];"
                 : "=r"(r0), "=r"(r1), "=r"(r2), "=r"(r3) : "r"(addr));
}
// bf16 mma (flash)
__device__ __forceinline__ void mma16816(float* c, uint32_t a0, uint32_t a1,
                                         uint32_t a2, uint32_t a3,
                                         uint32_t b0, uint32_t b1)
{
    asm volatile(
        "mma.sync.aligned.m16n8k16.row.col.f32.bf16.bf16.f32 "
        "{%0,%1,%2,%3}, {%4,%5,%6,%7}, {%8,%9}, {%0,%1,%2,%3};"
        : "+f"(c[0]), "+f"(c[1]), "+f"(c[2]), "+f"(c[3])
        : "r"(a0), "r"(a1), "r"(a2), "r"(a3), "r"(b0), "r"(b1));
}
// fp16 mma (projection GEMMs)
__device__ __forceinline__ void mma16816h(float* c, uint32_t a0, uint32_t a1,
                                          uint32_t a2, uint32_t a3,
                                          uint32_t b0, uint32_t b1)
{
    asm volatile(
        "mma.sync.aligned.m16n8k16.row.col.f32.f16.f16.f32 "
        "{%0,%1,%2,%3}, {%4,%5,%6,%7}, {%8,%9}, {%0,%1,%2,%3};"
        : "+f"(c[0]), "+f"(c[1]), "+f"(c[2]), "+f"(c[3])
        : "r"(a0), "r"(a1), "r"(a2), "r"(a3), "r"(b0), "r"(b1));
}
__device__ __forceinline__ uint32_t packbf(float x, float y)
{
    __nv_bfloat162 t = __floats2bfloat162_rn(x, y);
    return *reinterpret_cast<uint32_t*>(&t);
}
// bf16 hi/lo split of a pair (x0 -> low element)
__device__ __forceinline__ void split2(float x0, float x1, uint32_t& h, uint32_t& l)
{
    float h0 = __bfloat162float(__float2bfloat16_rn(x0));
    float h1 = __bfloat162float(__float2bfloat16_rn(x1));
    h = packbf(h0, h1);
    l = packbf(x0 - h0, x1 - h1);
}
// fp16 hi/lo split of a pair
__device__ __forceinline__ void split2h(float x0, float x1, uint32_t& h, uint32_t& l)
{
    __half2 hh = __floats2half2_rn(x0, x1);
    float h0 = __low2float(hh), h1 = __high2float(hh);
    __half2 ll = __floats2half2_rn(x0 - h0, x1 - h1);
    h = *reinterpret_cast<uint32_t*>(&hh);
    l = *reinterpret_cast<uint32_t*>(&ll);
}
__device__ __forceinline__ void cpa16(uint32_t saddr, const void* gaddr)
{
    asm volatile("cp.async.cg.shared.global [%0], [%1], 16;"
                 :: "r"(saddr), "l"(gaddr));
}
__device__ __forceinline__ void cpa_commit()
{
    asm volatile("cp.async.commit_group;" ::: "memory");
}
template <int N>
__device__ __forceinline__ void cpa_wait()
{
    asm volatile("cp.async.wait_group %0;" :: "n"(N) : "memory");
}

// ---------------------------------------------------------------------------
// presplits
// ---------------------------------------------------------------------------
__global__ void presplit2h_kernel(const float* __restrict__ src,
                                  __half* __restrict__ dh,
                                  __half* __restrict__ dl, int n2)
{
    int i = blockIdx.x * blockDim.x + threadIdx.x;
    if (i >= n2) return;
    float2 v = ((const float2*)src)[i];
    uint32_t h, l;
    split2h(v.x, v.y, h, l);
    ((uint32_t*)dh)[i] = h;
    ((uint32_t*)dl)[i] = l;
}
// both weight matrices -> fp16 single, one launch
__global__ void presplit_w_kernel(const float* __restrict__ Wq,
                                  const float* __restrict__ Wd,
                                  __half* __restrict__ dwq,
                                  __half* __restrict__ dwd)
{
    const int NQ = DM * QKVN / 2;
    const int ND = DM * DM / 2;
    int i = blockIdx.x * blockDim.x + threadIdx.x;
    if (i < NQ) {
        float2 v = ((const float2*)Wq)[i];
        ((__half2*)dwq)[i] = __floats2half2_rn(v.x, v.y);
    } else if (i - NQ < ND) {
        int j = i - NQ;
        float2 v = ((const float2*)Wd)[j];
        ((__half2*)dwd)[j] = __floats2half2_rn(v.x, v.y);
    }
}

// ---------------------------------------------------------------------------
// fp16 2-term GEMM: (Ah+Al)[M,K]*Bh[K,N] + bias[N]
// CTA tile 128x128, K-step 32, 8 warps (warp tile 32x64), cp.async 2-stage,
// 2 CTAs/SM.  mode 0: C += fp32 store (dense output).
//            mode 1: fused RoPE + bf16 hi/lo split -> g_q/k/v (QKV path).
// ---------------------------------------------------------------------------
#define GA_STRIDE 40
#define GB_STRIDE 136
#define GA_BYTES  (128*GA_STRIDE*2)             // 10240
#define GB_BYTES  (32*GB_STRIDE*2)              // 8704
#define GBUF      (2*GA_BYTES + GB_BYTES)       // 29184
#define GEMM_SMEM (2*GBUF)                      // 58368

__global__ __launch_bounds__(256, 2)
void gemm_mma_kernel(const __half* __restrict__ Ah,
                     const __half* __restrict__ Al,
                     const __half* __restrict__ Bh,
                     const float* __restrict__ bias,
                     float* __restrict__ C,
                     const float* __restrict__ fc,
                     int N, int K, int mode)
{
    extern __shared__ char gsm[];
    const int tid = threadIdx.x;
    const int warp = tid >> 5, lane = tid & 31;
    const int g = lane >> 3, ri = lane & 7;
    const int wm = warp & 3, wn = warp >> 2;
    const int m0 = blockIdx.y * 128, n0 = blockIdx.x * 128;

    const int a_r = tid >> 2, a_c = (tid & 3) << 3;   // rows +i*64
    const int b_r = tid >> 4, b_c = (tid & 15) << 3;  // rows +i*16

    const uint32_t sbase = (uint32_t)__cvta_generic_to_shared(gsm);
    const int nk = K >> 5;

    auto load_tile = [&](int kt, int buf) {
        const uint32_t bb = sbase + buf * GBUF;
#pragma unroll
        for (int i = 0; i < 2; ++i) {
            size_t ga = (size_t)(m0 + a_r + i * 64) * K + kt * 32 + a_c;
            uint32_t sa = bb + (uint32_t)(((a_r + i*64) * GA_STRIDE + a_c) * 2);
            cpa16(sa,            Ah + ga);
            cpa16(sa + GA_BYTES, Al + ga);
            size_t gb = (size_t)(kt * 32 + b_r + i * 16) * N + n0 + b_c;
            uint32_t sb = bb + 2*GA_BYTES + (uint32_t)(((b_r + i*16) * GB_STRIDE + b_c) * 2);
            cpa16(sb, Bh + gb);
        }
        cpa_commit();
    };

    float acc[2][8][4];
#pragma unroll
    for (int mf = 0; mf < 2; ++mf)
#pragma unroll
        for (int nf = 0; nf < 8; ++nf)
#pragma unroll
            for (int c = 0; c < 4; ++c) acc[mf][nf][c] = 0.f;

    const uint32_t aoff = (uint32_t)(((wm*32 + ri + (g&1)*8) * GA_STRIDE + (g>>1)*8) * 2);
    const uint32_t boff = (uint32_t)(((ri + (g&1)*8) * GB_STRIDE + wn*64 + (g>>1)*8) * 2);

    load_tile(0, 0);
    load_tile(1, 1);
    cpa_wait<1>();
    __syncthreads();

    for (int kt = 0; kt < nk; ++kt) {
        const int buf = kt & 1;
        const uint32_t sAh = sbase + buf * GBUF;
        const uint32_t sAl = sAh + GA_BYTES;
        const uint32_t sBh = sAh + 2*GA_BYTES;

#pragma unroll
        for (int k16 = 0; k16 < 2; ++k16) {
            uint32_t ah[2][4], al[2][4];
#pragma unroll
            for (int mf = 0; mf < 2; ++mf) {
                uint32_t o = aoff + (uint32_t)(mf * 16 * GA_STRIDE * 2) + k16 * 32;
                ldsm4(ah[mf][0], ah[mf][1], ah[mf][2], ah[mf][3], sAh + o);
                ldsm4(al[mf][0], al[mf][1], al[mf][2], al[mf][3], sAl + o);
            }
#pragma unroll
            for (int nfp = 0; nfp < 4; ++nfp) {
                uint32_t bh[4];
                uint32_t o = boff + (uint32_t)(k16 * 16 * GB_STRIDE * 2) + nfp * 32;
                ldsm4t(bh[0], bh[1], bh[2], bh[3], sBh + o);
#pragma unroll
                for (int mf = 0; mf < 2; ++mf) {
                    mma16816h(acc[mf][2*nfp],   ah[mf][0],ah[mf][1],ah[mf][2],ah[mf][3], bh[0],bh[1]);
                    mma16816h(acc[mf][2*nfp+1], ah[mf][0],ah[mf][1],ah[mf][2],ah[mf][3], bh[2],bh[3]);
                }
#pragma unroll
                for (int mf = 0; mf < 2; ++mf) {
                    mma16816h(acc[mf][2*nfp],   al[mf][0],al[mf][1],al[mf][2],al[mf][3], bh[0],bh[1]);
                    mma16816h(acc[mf][2*nfp+1], al[mf][0],al[mf][1],al[mf][2],al[mf][3], bh[2],bh[3]);
                }
            }
        }

        __syncthreads();
        if (kt + 2 < nk) load_tile(kt + 2, buf);
        if (kt + 1 < nk) {
            cpa_wait<1>();
            __syncthreads();
        }
    }

    if (mode == 0) {
        // dense epilogue: add bias, store fp32
#pragma unroll
        for (int mf = 0; mf < 2; ++mf) {
            int row = m0 + wm * 32 + mf * 16 + (lane >> 2);
#pragma unroll
            for (int nf = 0; nf < 8; ++nf) {
                int col = n0 + wn * 64 + nf * 8 + 2 * (lane & 3);
                float b0 = bias[col], b1 = bias[col + 1];
                *(float2*)(C + (size_t)row * N + col) =
                    make_float2(acc[mf][nf][0] + b0, acc[mf][nf][1] + b1);
                *(float2*)(C + (size_t)(row + 8) * N + col) =
                    make_float2(acc[mf][nf][2] + b0, acc[mf][nf][3] + b1);
            }
        }
    } else {
        // QKV epilogue: bias + RoPE (Q,K) + bf16 hi/lo split, write g_q/k/v
        const int part = n0 >> 11;        // 0=Q, 1=K, 2=V (CTA lies in one part)
        const float qs = 0.08838834764831845f;   // 128^-0.5
#pragma unroll
        for (int mf = 0; mf < 2; ++mf) {
            int row = m0 + wm * 32 + mf * 16 + (lane >> 2);
#pragma unroll
            for (int nf = 0; nf < 8; ++nf) {
                int col = n0 + wn * 64 + nf * 8 + 2 * (lane & 3);
                float b0 = bias[col], b1 = bias[col + 1];
                float y0 = acc[mf][nf][0] + b0, y1 = acc[mf][nf][1] + b1;  // row
                float z0 = acc[mf][nf][2] + b0, z1 = acc[mf][nf][3] + b1;  // row+8
                int dcol = col & 2047;
                int h  = dcol >> 7;
                int hd = dcol & 127;
                int i  = hd >> 1;
                size_t o0 = ((size_t)h * SEQ + row) * HD + hd;
                size_t o1 = o0 + (size_t)8 * HD;
                uint32_t hh, ll;
                if (part == 2) {          // V: passthrough split
                    split2(y0, y1, hh, ll);
                    *(uint32_t*)&g_vh[o0] = hh; *(uint32_t*)&g_vl[o0] = ll;
                    split2(z0, z1, hh, ll);
                    *(uint32_t*)&g_vh[o1] = hh; *(uint32_t*)&g_vl[o1] = ll;
                } else {
                    float2 cs0 = ((const float2*)fc)[row * 64 + i];
                    float2 cs1 = ((const float2*)fc)[(row + 8) * 64 + i];
                    float r0 = y0 * cs0.x - y1 * cs0.y;
                    float r1 = y1 * cs0.x + y0 * cs0.y;
                    float t0 = z0 * cs1.x - z1 * cs1.y;
                    float t1 = z1 * cs1.x + z0 * cs1.y;
                    if (part == 0) {      // Q: pre-scale
                        r0 *= qs; r1 *= qs; t0 *= qs; t1 *= qs;
                        split2(r0, r1, hh, ll);
                        *(uint32_t*)&g_qh[o0] = hh; *(uint32_t*)&g_ql[o0] = ll;
                        split2(t0, t1, hh, ll);
                        *(uint32_t*)&g_qh[o1] = hh; *(uint32_t*)&g_ql[o1] = ll;
                    } else {              // K
                        split2(r0, r1, hh, ll);
                        *(uint32_t*)&g_kh[o0] = hh; *(uint32_t*)&g_kl[o0] = ll;
                        split2(t0, t1, hh, ll);
                        *(uint32_t*)&g_kh[o1] = hh; *(uint32_t*)&g_kl[o1] = ll;
                    }
                }
            }
        }
    }
}

// ---------------------------------------------------------------------------
// Tensor-core flash attention (bf16 hi/lo split, fp32 softmax/accum).
// Epilogue writes ctx as fp16 hi/lo (A of the dense GEMM).
// ---------------------------------------------------------------------------
#define FL_STRIDE 136
#define FL_Q_ELE  (128*FL_STRIDE)
#define FL_K_ELE  (64*FL_STRIDE)
#define FLASH_SMEM ((2*FL_Q_ELE + 4*FL_K_ELE) * 2)

__global__ __launch_bounds__(256, 1)
void flash_attn_mma_kernel()
{
    extern __shared__ __nv_bfloat16 sm[];
    __nv_bfloat16* Qh = sm;
    __nv_bfloat16* Ql = Qh + FL_Q_ELE;
    __nv_bfloat16* Kh = Ql + FL_Q_ELE;
    __nv_bfloat16* Kl = Kh + FL_K_ELE;
    __nv_bfloat16* Vh = Kl + FL_K_ELE;
    __nv_bfloat16* Vl = Vh + FL_K_ELE;

    const int h    = blockIdx.y;
    const int tid  = threadIdx.x;
    const int warp = tid >> 5, lane = tid & 31;
    const int g = lane >> 3, ri = lane & 7;

    const __nv_bfloat16* gQh = g_qh + (size_t)h * SEQ * HD;
    const __nv_bfloat16* gQl = g_ql + (size_t)h * SEQ * HD;
    const __nv_bfloat16* gKh = g_kh + (size_t)h * SEQ * HD;
    const __nv_bfloat16* gKl = g_kl + (size_t)h * SEQ * HD;
    const __nv_bfloat16* gVh = g_vh + (size_t)h * SEQ * HD;
    const __nv_bfloat16* gVl = g_vl + (size_t)h * SEQ * HD;

    const uint32_t sQh = (uint32_t)__cvta_generic_to_shared(Qh);
    const uint32_t sQl = (uint32_t)__cvta_generic_to_shared(Ql);
    const uint32_t sKh = (uint32_t)__cvta_generic_to_shared(Kh);
    const uint32_t sKl = (uint32_t)__cvta_generic_to_shared(Kl);
    const uint32_t sVh = (uint32_t)__cvta_generic_to_shared(Vh);
    const uint32_t sVl = (uint32_t)__cvta_generic_to_shared(Vl);

    const uint32_t aQoff = (uint32_t)(((warp*16 + ri + (g&1)*8) * FL_STRIDE + (g>>1)*8) * 2);
    const uint32_t bKoff = (uint32_t)(((ri + (g>>1)*8) * FL_STRIDE + (g&1)*8) * 2);
    const uint32_t bVoff = (uint32_t)(((ri + (g&1)*8) * FL_STRIDE + (g>>1)*8) * 2);

    const int bx = blockIdx.x;

    for (int pass = 0; pass < 2; ++pass) {
        const int qt = pass ? bx : (15 - bx);

        __syncthreads();
#pragma unroll
        for (int t = 0; t < 8; ++t) {
            int idx = tid + t * 256;
            int r = idx >> 4, c8 = (idx & 15) << 3;
            size_t gsrc = (size_t)(qt * 128 + r) * HD + c8;
            *(uint4*)&Qh[r * FL_STRIDE + c8] = *(const uint4*)&gQh[gsrc];
            *(uint4*)&Ql[r * FL_STRIDE + c8] = *(const uint4*)&gQl[gsrc];
        }

        float O[16][4];
        float m0 = -1e30f, m1 = -1e30f, l0 = 0.f, l1 = 0.f;
#pragma unroll
        for (int t = 0; t < 16; ++t)
#pragma unroll
            for (int c = 0; c < 4; ++c) O[t][c] = 0.f;

        const int jmax = 2 * qt + 1;
        for (int j = 0; j <= jmax; ++j) {
            __syncthreads();
#pragma unroll
            for (int t = 0; t < 4; ++t) {
                int idx = tid + t * 256;
                int r = idx >> 4, c8 = (idx & 15) << 3;
                size_t gsrc = (size_t)(j * 64 + r) * HD + c8;
                *(uint4*)&Kh[r * FL_STRIDE + c8] = *(const uint4*)&gKh[gsrc];
                *(uint4*)&Kl[r * FL_STRIDE + c8] = *(const uint4*)&gKl[gsrc];
                *(uint4*)&Vh[r * FL_STRIDE + c8] = *(const uint4*)&gVh[gsrc];
                *(uint4*)&Vl[r * FL_STRIDE + c8] = *(const uint4*)&gVl[gsrc];
            }
            __syncthreads();

            float S[8][4];
#pragma unroll
            for (int t = 0; t < 8; ++t)
#pragma unroll
                for (int c = 0; c < 4; ++c) S[t][c] = 0.f;

#pragma unroll
            for (int kc = 0; kc < 8; ++kc) {
                uint32_t qh0,qh1,qh2,qh3, ql0,ql1,ql2,ql3;
                ldsm4(qh0,qh1,qh2,qh3, sQh + aQoff + kc*32);
                ldsm4(ql0,ql1,ql2,ql3, sQl + aQoff + kc*32);
#pragma unroll
                for (int np = 0; np < 4; ++np) {
                    uint32_t kh0,kh1,kh2,kh3, kl0,kl1,kl2,kl3;
                    uint32_t o = bKoff + (uint32_t)(np*16*FL_STRIDE*2) + kc*32;
                    ldsm4(kh0,kh1,kh2,kh3, sKh + o);
                    ldsm4(kl0,kl1,kl2,kl3, sKl + o);
                    mma16816(S[2*np],   qh0,qh1,qh2,qh3, kh0,kh1);
                    mma16816(S[2*np],   ql0,ql1,ql2,ql3, kh0,kh1);
                    mma16816(S[2*np],   qh0,qh1,qh2,qh3, kl0,kl1);
                    mma16816(S[2*np+1], qh0,qh1,qh2,qh3, kh2,kh3);
                    mma16816(S[2*np+1], ql0,ql1,ql2,ql3, kh2,kh3);
                    mma16816(S[2*np+1], qh0,qh1,qh2,qh3, kl2,kl3);
                }
            }

            const int row0 = qt * 128 + warp * 16 + (lane >> 2);
            if (j >= 2 * qt) {
#pragma unroll
                for (int t = 0; t < 8; ++t) {
                    int col = j * 64 + t * 8 + 2 * (lane & 3);
#pragma unroll
                    for (int c = 0; c < 4; ++c) {
                        int cc = col + (c & 1);
                        int rr = row0 + ((c >= 2) ? 8 : 0);
                        if (cc > rr) S[t][c] = -1e30f;
                    }
                }
            }

            float mx0 = -1e30f, mx1 = -1e30f;
#pragma unroll
            for (int t = 0; t < 8; ++t) {
                mx0 = fmaxf(mx0, fmaxf(S[t][0], S[t][1]));
                mx1 = fmaxf(mx1, fmaxf(S[t][2], S[t][3]));
            }
            mx0 = fmaxf(mx0, __shfl_xor_sync(0xffffffffu, mx0, 1));
            mx0 = fmaxf(mx0, __shfl_xor_sync(0xffffffffu, mx0, 2));
            mx1 = fmaxf(mx1, __shfl_xor_sync(0xffffffffu, mx1, 1));
            mx1 = fmaxf(mx1, __shfl_xor_sync(0xffffffffu, mx1, 2));
            float mn0 = fmaxf(m0, mx0), mn1 = fmaxf(m1, mx1);
            float al0 = __expf(m0 - mn0), al1 = __expf(m1 - mn1);
            float rs0 = 0.f, rs1 = 0.f;
#pragma unroll
            for (int t = 0; t < 8; ++t) {
                S[t][0] = __expf(S[t][0] - mn0);
                S[t][1] = __expf(S[t][1] - mn0);
                S[t][2] = __expf(S[t][2] - mn1);
                S[t][3] = __expf(S[t][3] - mn1);
                rs0 += S[t][0] + S[t][1];
                rs1 += S[t][2] + S[t][3];
            }
            rs0 += __shfl_xor_sync(0xffffffffu, rs0, 1);
            rs0 += __shfl_xor_sync(0xffffffffu, rs0, 2);
            rs1 += __shfl_xor_sync(0xffffffffu, rs1, 1);
            rs1 += __shfl_xor_sync(0xffffffffu, rs1, 2);
            l0 = l0 * al0 + rs0;  m0 = mn0;
            l1 = l1 * al1 + rs1;  m1 = mn1;
#pragma unroll
            for (int t = 0; t < 16; ++t) {
                O[t][0] *= al0; O[t][1] *= al0;
                O[t][2] *= al1; O[t][3] *= al1;
            }

#pragma unroll
            for (int kc2 = 0; kc2 < 4; ++kc2) {
                uint32_t ph0,ph1,ph2,ph3, pl0,pl1,pl2,pl3;
                split2(S[2*kc2][0],   S[2*kc2][1],   ph0, pl0);
                split2(S[2*kc2][2],   S[2*kc2][3],   ph1, pl1);
                split2(S[2*kc2+1][0], S[2*kc2+1][1], ph2, pl2);
                split2(S[2*kc2+1][2], S[2*kc2+1][3], ph3, pl3);
#pragma unroll
                for (int np = 0; np < 8; ++np) {
                    uint32_t vh0,vh1,vh2,vh3, vl0,vl1,vl2,vl3;
                    uint32_t o = bVoff + (uint32_t)(kc2*16*FL_STRIDE*2) + np*32;
                    ldsm4t(vh0,vh1,vh2,vh3, sVh + o);
                    ldsm4t(vl0,vl1,vl2,vl3, sVl + o);
                    mma16816(O[2*np],   ph0,ph1,ph2,ph3, vh0,vh1);
                    mma16816(O[2*np],   pl0,pl1,pl2,pl3, vh0,vh1);
                    mma16816(O[2*np],   ph0,ph1,ph2,ph3, vl0,vl1);
                    mma16816(O[2*np+1], ph0,ph1,ph2,ph3, vh2,vh3);
                    mma16816(O[2*np+1], pl0,pl1,pl2,pl3, vh2,vh3);
                    mma16816(O[2*np+1], ph0,ph1,ph2,ph3, vl2,vl3);
                }
            }
        }

        // normalize + store ctx as fp16 hi/lo, [S, D] layout (head h cols)
        float inv0 = 1.f / l0, inv1 = 1.f / l1;
        int grow = qt * 128 + warp * 16 + (lane >> 2);
        size_t off0 = (size_t)grow * DM + h * HD;
        size_t off1 = off0 + (size_t)8 * DM;
#pragma unroll
        for (int t = 0; t < 16; ++t) {
            int c = t * 8 + 2 * (lane & 3);
            uint32_t hh, ll;
            split2h(O[t][0] * inv0, O[t][1] * inv0, hh, ll);
            *(uint32_t*)&g_ch[off0 + c] = hh;
            *(uint32_t*)&g_cl[off0 + c] = ll;
            split2h(O[t][2] * inv1, O[t][3] * inv1, hh, ll);
            *(uint32_t*)&g_ch[off1 + c] = hh;
            *(uint32_t*)&g_cl[off1 + c] = ll;
        }
    }
}

// ---------------------------------------------------------------------------
extern "C" void kernel_launch(void* const* d_in, const int* in_sizes, int n_in,
                              void* d_out, int out_size)
{
    const float* x    = (const float*)d_in[0];
    const float* fc   = (const float*)d_in[1];
    // d_in[2] = input_pos (arange -> identity scatter, unused)
    const float* Wqkv = (const float*)d_in[3];
    const float* bqkv = (const float*)d_in[4];
    const float* Wd   = (const float*)d_in[5];
    const float* bd   = (const float*)d_in[6];
    float* out = (float*)d_out;

    __half *xh, *xl, *wqh, *wdh, *ch, *cl;
    cudaGetSymbolAddress((void**)&xh,  g_xh);  cudaGetSymbolAddress((void**)&xl,  g_xl);
    cudaGetSymbolAddress((void**)&wqh, g_wqh);
    cudaGetSymbolAddress((void**)&wdh, g_wdh);
    cudaGetSymbolAddress((void**)&ch,  g_ch);  cudaGetSymbolAddress((void**)&cl,  g_cl);

    cudaFuncSetAttribute(gemm_mma_kernel,
                         cudaFuncAttributeMaxDynamicSharedMemorySize, GEMM_SMEM);
    cudaFuncSetAttribute(flash_attn_mma_kernel,
                         cudaFuncAttributeMaxDynamicSharedMemorySize, FLASH_SMEM);

    // 0) presplit inputs: x -> fp16 hi/lo, both weights -> fp16 single (1 launch)
    presplit2h_kernel<<<(SEQ*DM/2 + 255)/256, 256>>>(x, xh, xl, SEQ*DM/2);
    {
        int total = DM*QKVN/2 + DM*DM/2;
        presplit_w_kernel<<<(total + 255)/256, 256>>>(Wqkv, Wd, wqh, wdh);
    }

    // 1) QKV projection + fused RoPE/split (mode 1): writes g_q/k/v hi/lo
    gemm_mma_kernel<<<dim3(QKVN/128, SEQ/128), 256, GEMM_SMEM>>>(
        xh, xl, wqh, bqkv, nullptr, fc, QKVN, DM, 1);

    // 2) causal flash attention (paired q-tiles: 8 x 16 CTAs); writes ctx fp16 hi/lo
    flash_attn_mma_kernel<<<dim3(8, NH), 256, FLASH_SMEM>>>();

    // 3) output projection (mode 0): ctx @ Wdense + bias -> out
    gemm_mma_kernel<<<dim3(DM/128, SEQ/128), 256, GEMM_SMEM>>>(
        ch, cl, wdh, bd, out, nullptr, DM, DM, 0);
}